// round 15
// baseline (speedup 1.0000x reference)
#include <cuda_runtime.h>
#include <cuda_fp16.h>
#include <cstdint>

// ---------------- problem constants ----------------
namespace {
constexpr int BB = 2, SS = 2048, DD = 2048, HH = 16, GG = 4, HD = 128;
constexpr float EPS = 1e-6f;
constexpr float SCALING = 0.08838834764831845f; // 1/sqrt(128)

// GEMM (fp16): 128x128 CTA tile, 8 warps (64x32), K-slice 64, 3-stage cp.async
constexpr int NSTAGE = 3;
constexpr int RSH = 72;                               // halfs per row (144B; 36 words % 32 = 4)
constexpr uint32_t TILE_BYTES = 128 * RSH * 2;        // 18432 per matrix
constexpr uint32_t STAGE_BYTES = 2 * TILE_BYTES;      // A + B = 36864
constexpr uint32_t GEMM_SMEM = NSTAGE * STAGE_BYTES;  // 110592

// attention: fp16 smem, row stride 136 halfs = 68 words (68 % 32 = 4)
constexpr int RSW = 68;                               // row stride in u32 words
constexpr uint32_t KW = 64 * RSW;                     // K tile words
constexpr uint32_t ATTN_SMEM = 2 * KW * 4;            // 34816 B
}

// ---------------- scratch (device globals; no allocation allowed) ----------------
__device__ float g_q[(size_t)BB * HH * SS * HD];   // [B,H,S,HD] fp32
__device__ float g_k[(size_t)BB * GG * SS * HD];
__device__ float g_v[(size_t)BB * GG * SS * HD];
// fp16 copies for GEMM consumption
__device__ __half g_xh[(size_t)BB * SS * DD];
__device__ __half g_wqh[(size_t)HH * HD * DD];
__device__ __half g_wkh[(size_t)GG * HD * DD];
__device__ __half g_wvh[(size_t)GG * HD * DD];
__device__ __half g_woh[(size_t)DD * HH * HD];
__device__ __half g_ctxh[(size_t)BB * SS * HH * HD]; // attention output (fp16)

// ---------------- helpers ----------------
__device__ __forceinline__ uint32_t pack_h2(float2 v) {
    uint32_t r;
    asm("cvt.rn.f16x2.f32 %0, %1, %2;" : "=r"(r) : "f"(v.y), "f"(v.x));
    return r;
}

__device__ __forceinline__ void mma16(float* c, const uint32_t* a, const uint32_t* b) {
    asm volatile(
        "mma.sync.aligned.m16n8k16.row.col.f32.f16.f16.f32 "
        "{%0,%1,%2,%3},{%4,%5,%6,%7},{%8,%9},{%0,%1,%2,%3};\n"
        : "+f"(c[0]), "+f"(c[1]), "+f"(c[2]), "+f"(c[3])
        : "r"(a[0]), "r"(a[1]), "r"(a[2]), "r"(a[3]), "r"(b[0]), "r"(b[1]));
}

__device__ __forceinline__ void ldmx4(uint32_t* r, uint32_t addr) {
    asm volatile(
        "ldmatrix.sync.aligned.m8n8.x4.shared.b16 {%0,%1,%2,%3}, [%4];"
        : "=r"(r[0]), "=r"(r[1]), "=r"(r[2]), "=r"(r[3]) : "r"(addr));
}

__device__ __forceinline__ void ldmx4t(uint32_t* r, uint32_t addr) {
    asm volatile(
        "ldmatrix.sync.aligned.m8n8.x4.trans.shared.b16 {%0,%1,%2,%3}, [%4];"
        : "=r"(r[0]), "=r"(r[1]), "=r"(r[2]), "=r"(r[3]) : "r"(addr));
}

__device__ __forceinline__ uint32_t smem_u32(const void* p) {
    uint32_t a;
    asm("{ .reg .u64 t; cvta.to.shared.u64 t, %1; cvt.u32.u64 %0, t; }" : "=r"(a) : "l"(p));
    return a;
}

__device__ __forceinline__ void cpasync16(uint32_t dst, const void* src) {
    asm volatile("cp.async.cg.shared.global [%0], [%1], 16;" :: "r"(dst), "l"(src));
}

// =====================================================================
// fp32 -> fp16 pre-pass over x, Wq, Wk, Wv, Wo (rn, once per value).
// =====================================================================
__global__ __launch_bounds__(256) void tofp16(
    const float4* __restrict__ x, const float4* __restrict__ wq,
    const float4* __restrict__ wk, const float4* __restrict__ wv,
    const float4* __restrict__ wo) {
    constexpr int N0 = (int)((size_t)BB * SS * DD / 4);
    constexpr int N1 = (int)((size_t)HH * HD * DD / 4);
    constexpr int N2 = (int)((size_t)GG * HD * DD / 4);
    constexpr int N3 = N2;
    constexpr int N4 = (int)((size_t)DD * HH * HD / 4);
    constexpr int NT = N0 + N1 + N2 + N3 + N4;
    for (int i = blockIdx.x * blockDim.x + threadIdx.x; i < NT; i += gridDim.x * blockDim.x) {
        const float4* s;
        uint2* d;
        int j = i;
        if (j < N0) { s = x; d = (uint2*)g_xh; }
        else if ((j -= N0) < N1) { s = wq; d = (uint2*)g_wqh; }
        else if ((j -= N1) < N2) { s = wk; d = (uint2*)g_wkh; }
        else if ((j -= N2) < N3) { s = wv; d = (uint2*)g_wvh; }
        else { j -= N3; s = wo; d = (uint2*)g_woh; }
        float4 v = s[j];
        d[j] = make_uint2(pack_h2(make_float2(v.x, v.y)), pack_h2(make_float2(v.z, v.w)));
    }
}

// =====================================================================
// GEMM: C[M,N] = A[M,K] * W[N,K]^T  (fp16 inputs, m16n8k16, fp32 accum)
// CTA 128x128, K-slice 64, 256 threads, 8 warps each 64x32 (2x4 grid),
// 3-stage cp.async, fp16 smem + ldmatrix.
// Dual-weight: blocks with bn >= nsplit use (W2, C2) with bn' = bn - nsplit
// (fuses the Wk and Wv GEMMs, which share A, into one launch).
// mode 0: C row-major fp32 [M,N].  mode 1: head layout dst[b, bn, s, :] fp32.
// =====================================================================
__global__ __launch_bounds__(256) void gemm_h(
    const __half* __restrict__ A, const __half* __restrict__ W,
    float* __restrict__ Cout, const __half* __restrict__ W2,
    float* __restrict__ C2, int nsplit, int N, int K, int mode, int HN) {
    extern __shared__ char smem[];
    const int tid = threadIdx.x;
    const int lane = tid & 31, wid = tid >> 5;
    const int wm = wid & 1, wn = wid >> 1;   // 2 (m) x 4 (n) warp grid
    const int g = lane >> 2, t = lane & 3;
    const int bm = blockIdx.y;
    int bn = blockIdx.x;

    const __half* Wsel = W;
    float* Csel = Cout;
    if (bn >= nsplit) { Wsel = W2; Csel = C2; bn -= nsplit; }

    const __half* Ag = A + (size_t)bm * 128 * K;
    const __half* Wg = Wsel + (size_t)bn * 128 * K;
    const int nk = K / 64;

    const uint32_t sb = smem_u32(smem);

    // ldmatrix per-lane address components (R14-proven)
    const int row_a = (lane & 7) + 8 * ((lane >> 3) & 1);
    const int col_a = 8 * (lane >> 4);
    const int row_b = (lane & 7) + 8 * (lane >> 4);
    const int col_b = 8 * ((lane >> 3) & 1);

    float acc[4][4][4];
#pragma unroll
    for (int i = 0; i < 4; i++)
#pragma unroll
        for (int j = 0; j < 4; j++)
#pragma unroll
            for (int q = 0; q < 4; q++) acc[i][j][q] = 0.f;

    // 8 cp.async per thread per stage (4 A + 4 B chunks of 16B = 8 halfs)
    auto loadstage = [&](int kt) {
        if (kt < nk) {
            const uint32_t sa = sb + (uint32_t)(kt % NSTAGE) * STAGE_BYTES;
            const uint32_t sw = sa + TILE_BYTES;
#pragma unroll
            for (int j = 0; j < 4; j++) {
                const int cc = tid + 256 * j;      // 0..1023
                const int row = cc >> 3, c16 = cc & 7;
                const uint32_t off = (uint32_t)row * (RSH * 2) + c16 * 16;
                cpasync16(sa + off, Ag + (size_t)row * K + kt * 64 + c16 * 8);
                cpasync16(sw + off, Wg + (size_t)row * K + kt * 64 + c16 * 8);
            }
        }
        asm volatile("cp.async.commit_group;" ::: "memory");
    };

    loadstage(0);
    loadstage(1);

    for (int kt = 0; kt < nk; kt++) {
        asm volatile("cp.async.wait_group 1;" ::: "memory");
        __syncthreads();
        loadstage(kt + 2);

        const uint32_t sA = sb + (uint32_t)(kt % NSTAGE) * STAGE_BYTES;
        const uint32_t sB = sA + TILE_BYTES;

#pragma unroll
        for (int ks = 0; ks < 4; ks++) {
            uint32_t af[4][4], bf[2][4];
#pragma unroll
            for (int mf = 0; mf < 4; mf++)
                ldmx4(af[mf], sA + (uint32_t)(wm * 64 + mf * 16 + row_a) * (RSH * 2)
                              + (uint32_t)(ks * 16 + col_a) * 2);
#pragma unroll
            for (int nfp = 0; nfp < 2; nfp++)
                ldmx4(bf[nfp], sB + (uint32_t)(wn * 32 + nfp * 16 + row_b) * (RSH * 2)
                               + (uint32_t)(ks * 16 + col_b) * 2);
#pragma unroll
            for (int mf = 0; mf < 4; mf++)
#pragma unroll
                for (int nfp = 0; nfp < 2; nfp++) {
                    mma16(acc[mf][2 * nfp], af[mf], bf[nfp]);
                    mma16(acc[mf][2 * nfp + 1], af[mf], bf[nfp] + 2);
                }
        }
    }

    // ---- epilogue ----
#pragma unroll
    for (int mf = 0; mf < 4; mf++) {
#pragma unroll
        for (int nf = 0; nf < 4; nf++) {
            const int row = bm * 128 + wm * 64 + mf * 16 + g;
            const int col = bn * 128 + wn * 32 + nf * 8 + 2 * t;
#pragma unroll
            for (int half = 0; half < 2; half++) {
                const int rr = row + half * 8;
                float2 val = make_float2(acc[mf][nf][half * 2], acc[mf][nf][half * 2 + 1]);
                if (mode == 0) {
                    *(float2*)(Csel + (size_t)rr * N + col) = val;
                } else {
                    const int b = rr >> 11, s = rr & (SS - 1);
                    const int h = col >> 7, hd = col & 127;
                    *(float2*)(Csel + ((size_t)(b * HN + h) * SS + s) * HD + hd) = val;
                }
            }
        }
    }
}

// =====================================================================
// Fused RMSNorm + RoPE (+ q scaling), in place (fp32 q/k). Unchanged.
// =====================================================================
__global__ __launch_bounds__(256) void rmsrope(
    const float* __restrict__ cosb, const float* __restrict__ sinb,
    const float* __restrict__ qw, const float* __restrict__ kw) {
    const int wid = threadIdx.x >> 5, lane = threadIdx.x & 31;
    const int row = blockIdx.x * 8 + wid;
    constexpr int QROWS = BB * HH * SS;

    float* base;
    const float* w;
    float extra;
    int s;
    if (row < QROWS) {
        base = g_q + (size_t)row * HD;
        w = qw;
        extra = SCALING;
        s = row & (SS - 1);
    } else {
        const int r = row - QROWS;
        base = g_k + (size_t)r * HD;
        w = kw;
        extra = 1.0f;
        s = r & (SS - 1);
    }

    float x0 = base[lane], x1 = base[lane + 32], x2 = base[lane + 64], x3 = base[lane + 96];
    float ssq = x0 * x0 + x1 * x1 + x2 * x2 + x3 * x3;
#pragma unroll
    for (int o = 16; o; o >>= 1) ssq += __shfl_xor_sync(0xffffffffu, ssq, o);
    const float inv = rsqrtf(ssq * (1.0f / HD) + EPS);

    const float n0 = x0 * inv * w[lane];
    const float n1 = x1 * inv * w[lane + 32];
    const float n2 = x2 * inv * w[lane + 64];
    const float n3 = x3 * inv * w[lane + 96];

    const float* cs = cosb + (size_t)s * HD;
    const float* sn = sinb + (size_t)s * HD;
    const float o0 = n0 * cs[lane] - n2 * sn[lane];
    const float o1 = n1 * cs[lane + 32] - n3 * sn[lane + 32];
    const float o2 = n2 * cs[lane + 64] + n0 * sn[lane + 64];
    const float o3 = n3 * cs[lane + 96] + n1 * sn[lane + 96];

    base[lane] = o0 * extra;
    base[lane + 32] = o1 * extra;
    base[lane + 64] = o2 * extra;
    base[lane + 96] = o3 * extra;
}

// =====================================================================
// Flash attention (causal), fp16 mma + fp16 smem + ldmatrix.
// (PROVEN R14 text, unchanged.)
// =====================================================================
__global__ __launch_bounds__(256, 1) void attn() {
    extern __shared__ uint32_t smw[];
    uint32_t* Ksw = smw;
    uint32_t* Vsw = smw + KW;
    uint32_t* Qsw = smw;

    const int tid = threadIdx.x;
    const int lane = tid & 31, wid = tid >> 5;
    const int g = lane >> 2, t = lane & 3;
    const uint32_t sbase = smem_u32(smw);
    const uint32_t sbK = sbase;
    const uint32_t sbV = sbase + KW * 4;

    const int row_s = (lane & 7) + 8 * (lane >> 4);
    const int col_s = 8 * ((lane >> 3) & 1);
    const int row_v = (lane & 7) + 8 * ((lane >> 3) & 1);
    const int col_v = 8 * (lane >> 4);

    const int qt = gridDim.x - 1 - blockIdx.x;
    const int bh = blockIdx.y;
    const int b = bh / HH, h = bh % HH;
    const int kvh = h / (HH / GG);

    const float* qp = g_q + ((size_t)(b * HH + h) * SS + qt * 128) * HD;
    const float* kp = g_k + ((size_t)(b * GG + kvh) * SS) * HD;
    const float* vp = g_v + ((size_t)(b * GG + kvh) * SS) * HD;

    // ---- stage Q tile (128x128) as fp16 ----
    {
        const int qr = tid >> 5;
        const int qc = (tid & 31) * 4;
#pragma unroll
        for (int i = 0; i < 16; i++) {
            const int rr = qr + i * 8;
            float4 v4 = *(const float4*)(qp + (size_t)rr * HD + qc);
            *(uint2*)&Qsw[rr * RSW + (qc >> 1)] =
                make_uint2(pack_h2(make_float2(v4.x, v4.y)), pack_h2(make_float2(v4.z, v4.w)));
        }
    }
    __syncthreads();

    uint32_t qf[8][4];
    {
        const int r = wid * 16;
#pragma unroll
        for (int ks = 0; ks < 8; ks++) {
            const int cw = ks * 8 + t;
            qf[ks][0] = Qsw[(r + g) * RSW + cw];
            qf[ks][1] = Qsw[(r + g + 8) * RSW + cw];
            qf[ks][2] = Qsw[(r + g) * RSW + cw + 4];
            qf[ks][3] = Qsw[(r + g + 8) * RSW + cw + 4];
        }
    }
    __syncthreads();

    float o[16][4];
#pragma unroll
    for (int i = 0; i < 16; i++)
#pragma unroll
        for (int j = 0; j < 4; j++) o[i][j] = 0.f;
    float mprev[2] = {-1e30f, -1e30f};
    float lsum[2] = {0.f, 0.f};

    const int jmax = 2 * qt + 1;
    for (int jt = 0; jt <= jmax; jt++) {
        {
            const int rr0 = tid >> 5;
            const int cc = (tid & 31) * 4;
#pragma unroll
            for (int i = 0; i < 8; i++) {
                const int rr = rr0 + i * 8;
                float4 k4 = *(const float4*)(kp + (size_t)(jt * 64 + rr) * HD + cc);
                *(uint2*)&Ksw[rr * RSW + (cc >> 1)] =
                    make_uint2(pack_h2(make_float2(k4.x, k4.y)),
                               pack_h2(make_float2(k4.z, k4.w)));
                float4 v4 = *(const float4*)(vp + (size_t)(jt * 64 + rr) * HD + cc);
                *(uint2*)&Vsw[rr * RSW + (cc >> 1)] =
                    make_uint2(pack_h2(make_float2(v4.x, v4.y)),
                               pack_h2(make_float2(v4.z, v4.w)));
            }
        }
        __syncthreads();

        float sc[8][4];
#pragma unroll
        for (int i = 0; i < 8; i++)
#pragma unroll
            for (int j = 0; j < 4; j++) sc[i][j] = 0.f;

#pragma unroll
        for (int ks = 0; ks < 8; ks++) {
#pragma unroll
            for (int nfp = 0; nfp < 4; nfp++) {
                uint32_t kf[4];
                const uint32_t addr = sbK +
                    ((uint32_t)(16 * nfp + row_s) * (RSW * 4)) +
                    (uint32_t)(16 * ks + col_s) * 2;
                ldmx4(kf, addr);
                mma16(sc[2 * nfp], qf[ks], kf);
                mma16(sc[2 * nfp + 1], qf[ks], kf + 2);
            }
        }

        if (jt >= 2 * qt) {
            const int rowg = qt * 128 + wid * 16 + g;
#pragma unroll
            for (int nf = 0; nf < 8; nf++) {
                const int colg = jt * 64 + nf * 8 + 2 * t;
                if (colg > rowg) sc[nf][0] = -1e30f;
                if (colg + 1 > rowg) sc[nf][1] = -1e30f;
                if (colg > rowg + 8) sc[nf][2] = -1e30f;
                if (colg + 1 > rowg + 8) sc[nf][3] = -1e30f;
            }
        }

#pragma unroll
        for (int r = 0; r < 2; r++) {
            float mx = -1e30f;
#pragma unroll
            for (int nf = 0; nf < 8; nf++)
                mx = fmaxf(mx, fmaxf(sc[nf][2 * r], sc[nf][2 * r + 1]));
            mx = fmaxf(mx, __shfl_xor_sync(0xffffffffu, mx, 1));
            mx = fmaxf(mx, __shfl_xor_sync(0xffffffffu, mx, 2));
            const float mnew = fmaxf(mprev[r], mx);
            const float corr = __expf(mprev[r] - mnew);
            float sum = 0.f;
#pragma unroll
            for (int nf = 0; nf < 8; nf++) {
                sc[nf][2 * r] = __expf(sc[nf][2 * r] - mnew);
                sc[nf][2 * r + 1] = __expf(sc[nf][2 * r + 1] - mnew);
                sum += sc[nf][2 * r] + sc[nf][2 * r + 1];
            }
            sum += __shfl_xor_sync(0xffffffffu, sum, 1);
            sum += __shfl_xor_sync(0xffffffffu, sum, 2);
            lsum[r] = lsum[r] * corr + sum;
            mprev[r] = mnew;
#pragma unroll
            for (int nf = 0; nf < 16; nf++) {
                o[nf][2 * r] *= corr;
                o[nf][2 * r + 1] *= corr;
            }
        }

#pragma unroll
        for (int ks = 0; ks < 4; ks++) {
            uint32_t pafr[4];
            pafr[0] = pack_h2(make_float2(sc[2 * ks][0], sc[2 * ks][1]));
            pafr[1] = pack_h2(make_float2(sc[2 * ks][2], sc[2 * ks][3]));
            pafr[2] = pack_h2(make_float2(sc[2 * ks + 1][0], sc[2 * ks + 1][1]));
            pafr[3] = pack_h2(make_float2(sc[2 * ks + 1][2], sc[2 * ks + 1][3]));
#pragma unroll
            for (int nfp = 0; nfp < 8; nfp++) {
                uint32_t vf[4];
                const uint32_t addr = sbV +
                    ((uint32_t)(16 * ks + row_v) * (RSW * 4)) +
                    (uint32_t)(16 * nfp + col_v) * 2;
                ldmx4t(vf, addr);
                mma16(o[2 * nfp], pafr, vf);
                mma16(o[2 * nfp + 1], pafr, vf + 2);
            }
        }
        __syncthreads();
    }

    // ---- epilogue: O/l -> ctx (fp16, packed) ----
    uint32_t* ctxw = (uint32_t*)g_ctxh;
    const float inv0 = 1.f / lsum[0];
    const float inv1 = 1.f / lsum[1];
    const int row0 = qt * 128 + wid * 16 + g;
#pragma unroll
    for (int nf = 0; nf < 16; nf++) {
        const int col = nf * 8 + 2 * t;
        ctxw[(((size_t)(b * SS + row0) * (HH * HD)) + h * HD + col) >> 1] =
            pack_h2(make_float2(o[nf][0] * inv0, o[nf][1] * inv0));
        ctxw[(((size_t)(b * SS + row0 + 8) * (HH * HD)) + h * HD + col) >> 1] =
            pack_h2(make_float2(o[nf][2] * inv1, o[nf][3] * inv1));
    }
}

// =====================================================================
// host launcher
// =====================================================================
extern "C" void kernel_launch(void* const* d_in, const int* in_sizes, int n_in,
                              void* d_out, int out_size) {
    (void)in_sizes; (void)n_in; (void)out_size;
    const float* x    = (const float*)d_in[0];
    // d_in[1] = mask (causal triu, known analytically; unused)
    const float* cosb = (const float*)d_in[2];
    const float* sinb = (const float*)d_in[3];
    const float* Wq   = (const float*)d_in[4];
    const float* Wk   = (const float*)d_in[5];
    const float* Wv   = (const float*)d_in[6];
    const float* Wo   = (const float*)d_in[7];
    const float* qw   = (const float*)d_in[8];
    const float* kw   = (const float*)d_in[9];
    float* out = (float*)d_out;

    float *qptr, *kptr, *vptr;
    __half *xh, *wqh, *wkh, *wvh, *woh, *ctxh;
    cudaGetSymbolAddress((void**)&qptr, g_q);
    cudaGetSymbolAddress((void**)&kptr, g_k);
    cudaGetSymbolAddress((void**)&vptr, g_v);
    cudaGetSymbolAddress((void**)&xh, g_xh);
    cudaGetSymbolAddress((void**)&wqh, g_wqh);
    cudaGetSymbolAddress((void**)&wkh, g_wkh);
    cudaGetSymbolAddress((void**)&wvh, g_wvh);
    cudaGetSymbolAddress((void**)&woh, g_woh);
    cudaGetSymbolAddress((void**)&ctxh, g_ctxh);

    cudaFuncSetAttribute(gemm_h, cudaFuncAttributeMaxDynamicSharedMemorySize, GEMM_SMEM);
    cudaFuncSetAttribute(attn, cudaFuncAttributeMaxDynamicSharedMemorySize, ATTN_SMEM);

    const int BIG = 1 << 30;
    // 0. fp16 pre-pass (x, Wq, Wk, Wv, Wo)
    tofp16<<<2048, 256>>>((const float4*)x, (const float4*)Wq, (const float4*)Wk,
                          (const float4*)Wv, (const float4*)Wo);
    // 1. Q projection (fp16 in, fp32 head-layout out)
    gemm_h<<<dim3(16, 32), 256, GEMM_SMEM>>>(xh, wqh, qptr, wqh, qptr, BIG,
                                             HH * HD, DD, 1, HH);
    // 1b. K+V projections fused in one launch (shared A, bn<4 -> K, bn>=4 -> V)
    gemm_h<<<dim3(8, 32), 256, GEMM_SMEM>>>(xh, wkh, kptr, wvh, vptr, 4,
                                            GG * HD, DD, 1, GG);
    // 2. RMSNorm + RoPE (+ q scaling), in place on q and k
    rmsrope<<<(BB * (HH + GG) * SS) / 8, 256>>>(cosb, sinb, qw, kw);
    // 3. flash attention (writes fp16 ctx)
    attn<<<dim3(SS / 128, BB * HH), 256, ATTN_SMEM>>>();
    // 4. output projection (fp16 in, fp32 out) -> d_out
    gemm_h<<<dim3(16, 32), 256, GEMM_SMEM>>>(ctxh, woh, out, woh, out, BIG,
                                             DD, HH * HD, 0, 0);
}

// round 16
// speedup vs baseline: 1.0429x; 1.0429x over previous
#include <cuda_runtime.h>
#include <cuda_fp16.h>
#include <cstdint>

// ---------------- problem constants ----------------
namespace {
constexpr int BB = 2, SS = 2048, DD = 2048, HH = 16, GG = 4, HD = 128;
constexpr float EPS = 1e-6f;
constexpr float SCALING = 0.08838834764831845f; // 1/sqrt(128)

// GEMM (fp16): 128x128 CTA tile, 8 warps (64x32), K-slice 64, 3-stage cp.async
constexpr int NSTAGE = 3;
constexpr int RSH = 72;                               // halfs per row (144B)
constexpr uint32_t TILE_BYTES = 128 * RSH * 2;        // 18432 per matrix
constexpr uint32_t STAGE_BYTES = 2 * TILE_BYTES;      // A + B = 36864
constexpr uint32_t GEMM_SMEM = NSTAGE * STAGE_BYTES;  // 110592

// attention: fp16 smem, row stride 136 halfs = 272 B (68 words % 32 = 4 -> conflict-free)
constexpr int RSW = 68;                               // row stride in u32 words
constexpr uint32_t KT_B = 64 * RSW * 4;               // 17408 B per K (or V) tile
constexpr uint32_t KVST_B = 2 * KT_B;                 // 34816 B per stage (K+V)
constexpr uint32_t ATTN_SMEM = 2 * KVST_B;            // 69632 B (2 stages; Q overlaps stage 1)
}

// ---------------- scratch (device globals; no allocation allowed) ----------------
__device__ float g_q[(size_t)BB * HH * SS * HD];   // fp32 (GEMM out, rope in)
__device__ float g_k[(size_t)BB * GG * SS * HD];
// fp16 tensors
__device__ __half g_qh[(size_t)BB * HH * SS * HD]; // rope out
__device__ __half g_kh[(size_t)BB * GG * SS * HD]; // rope out
__device__ __half g_vh[(size_t)BB * GG * SS * HD]; // V GEMM out (mode 2)
__device__ __half g_xh[(size_t)BB * SS * DD];
__device__ __half g_wqh[(size_t)HH * HD * DD];
__device__ __half g_wkh[(size_t)GG * HD * DD];
__device__ __half g_wvh[(size_t)GG * HD * DD];
__device__ __half g_woh[(size_t)DD * HH * HD];
__device__ __half g_ctxh[(size_t)BB * SS * HH * HD];

// ---------------- helpers ----------------
__device__ __forceinline__ uint32_t pack_h2(float2 v) {
    uint32_t r;
    asm("cvt.rn.f16x2.f32 %0, %1, %2;" : "=r"(r) : "f"(v.y), "f"(v.x));
    return r;
}

__device__ __forceinline__ void mma16(float* c, const uint32_t* a, const uint32_t* b) {
    asm volatile(
        "mma.sync.aligned.m16n8k16.row.col.f32.f16.f16.f32 "
        "{%0,%1,%2,%3},{%4,%5,%6,%7},{%8,%9},{%0,%1,%2,%3};\n"
        : "+f"(c[0]), "+f"(c[1]), "+f"(c[2]), "+f"(c[3])
        : "r"(a[0]), "r"(a[1]), "r"(a[2]), "r"(a[3]), "r"(b[0]), "r"(b[1]));
}

__device__ __forceinline__ void ldmx4(uint32_t* r, uint32_t addr) {
    asm volatile(
        "ldmatrix.sync.aligned.m8n8.x4.shared.b16 {%0,%1,%2,%3}, [%4];"
        : "=r"(r[0]), "=r"(r[1]), "=r"(r[2]), "=r"(r[3]) : "r"(addr));
}

__device__ __forceinline__ void ldmx4t(uint32_t* r, uint32_t addr) {
    asm volatile(
        "ldmatrix.sync.aligned.m8n8.x4.trans.shared.b16 {%0,%1,%2,%3}, [%4];"
        : "=r"(r[0]), "=r"(r[1]), "=r"(r[2]), "=r"(r[3]) : "r"(addr));
}

__device__ __forceinline__ uint32_t smem_u32(const void* p) {
    uint32_t a;
    asm("{ .reg .u64 t; cvta.to.shared.u64 t, %1; cvt.u32.u64 %0, t; }" : "=r"(a) : "l"(p));
    return a;
}

__device__ __forceinline__ void cpasync16(uint32_t dst, const void* src) {
    asm volatile("cp.async.cg.shared.global [%0], [%1], 16;" :: "r"(dst), "l"(src));
}

// =====================================================================
// fp32 -> fp16 pre-pass over x, Wq, Wk, Wv, Wo (rn, once per value).
// =====================================================================
__global__ __launch_bounds__(256) void tofp16(
    const float4* __restrict__ x, const float4* __restrict__ wq,
    const float4* __restrict__ wk, const float4* __restrict__ wv,
    const float4* __restrict__ wo) {
    constexpr int N0 = (int)((size_t)BB * SS * DD / 4);
    constexpr int N1 = (int)((size_t)HH * HD * DD / 4);
    constexpr int N2 = (int)((size_t)GG * HD * DD / 4);
    constexpr int N3 = N2;
    constexpr int N4 = (int)((size_t)DD * HH * HD / 4);
    constexpr int NT = N0 + N1 + N2 + N3 + N4;
    for (int i = blockIdx.x * blockDim.x + threadIdx.x; i < NT; i += gridDim.x * blockDim.x) {
        const float4* s;
        uint2* d;
        int j = i;
        if (j < N0) { s = x; d = (uint2*)g_xh; }
        else if ((j -= N0) < N1) { s = wq; d = (uint2*)g_wqh; }
        else if ((j -= N1) < N2) { s = wk; d = (uint2*)g_wkh; }
        else if ((j -= N2) < N3) { s = wv; d = (uint2*)g_wvh; }
        else { j -= N3; s = wo; d = (uint2*)g_woh; }
        float4 v = s[j];
        d[j] = make_uint2(pack_h2(make_float2(v.x, v.y)), pack_h2(make_float2(v.z, v.w)));
    }
}

// =====================================================================
// GEMM: C[M,N] = A[M,K] * W[N,K]^T  (fp16 inputs, m16n8k16, fp32 accum)
// CTA 128x128, K-slice 64, 256 threads, 8 warps (64x32), 3-stage cp.async.
// Dual-weight: bn >= nsplit -> (W2, C2, mode2).
// mode 0: fp32 row-major. mode 1: fp32 head layout. mode 2: fp16 head layout.
// =====================================================================
__global__ __launch_bounds__(256) void gemm_h(
    const __half* __restrict__ A, const __half* __restrict__ W,
    void* __restrict__ Cout, const __half* __restrict__ W2,
    void* __restrict__ C2, int nsplit, int N, int K, int mode, int mode2, int HN) {
    extern __shared__ char smem[];
    const int tid = threadIdx.x;
    const int lane = tid & 31, wid = tid >> 5;
    const int wm = wid & 1, wn = wid >> 1;
    const int g = lane >> 2, t = lane & 3;
    const int bm = blockIdx.y;
    int bn = blockIdx.x;

    const __half* Wsel = W;
    void* Csel = Cout;
    int mymode = mode;
    if (bn >= nsplit) { Wsel = W2; Csel = C2; mymode = mode2; bn -= nsplit; }

    const __half* Ag = A + (size_t)bm * 128 * K;
    const __half* Wg = Wsel + (size_t)bn * 128 * K;
    const int nk = K / 64;

    const uint32_t sb = smem_u32(smem);

    const int row_a = (lane & 7) + 8 * ((lane >> 3) & 1);
    const int col_a = 8 * (lane >> 4);
    const int row_b = (lane & 7) + 8 * (lane >> 4);
    const int col_b = 8 * ((lane >> 3) & 1);

    float acc[4][4][4];
#pragma unroll
    for (int i = 0; i < 4; i++)
#pragma unroll
        for (int j = 0; j < 4; j++)
#pragma unroll
            for (int q = 0; q < 4; q++) acc[i][j][q] = 0.f;

    auto loadstage = [&](int kt) {
        if (kt < nk) {
            const uint32_t sa = sb + (uint32_t)(kt % NSTAGE) * STAGE_BYTES;
            const uint32_t sw = sa + TILE_BYTES;
#pragma unroll
            for (int j = 0; j < 4; j++) {
                const int cc = tid + 256 * j;
                const int row = cc >> 3, c16 = cc & 7;
                const uint32_t off = (uint32_t)row * (RSH * 2) + c16 * 16;
                cpasync16(sa + off, Ag + (size_t)row * K + kt * 64 + c16 * 8);
                cpasync16(sw + off, Wg + (size_t)row * K + kt * 64 + c16 * 8);
            }
        }
        asm volatile("cp.async.commit_group;" ::: "memory");
    };

    loadstage(0);
    loadstage(1);

    for (int kt = 0; kt < nk; kt++) {
        asm volatile("cp.async.wait_group 1;" ::: "memory");
        __syncthreads();
        loadstage(kt + 2);

        const uint32_t sA = sb + (uint32_t)(kt % NSTAGE) * STAGE_BYTES;
        const uint32_t sB = sA + TILE_BYTES;

#pragma unroll
        for (int ks = 0; ks < 4; ks++) {
            uint32_t af[4][4], bf[2][4];
#pragma unroll
            for (int mf = 0; mf < 4; mf++)
                ldmx4(af[mf], sA + (uint32_t)(wm * 64 + mf * 16 + row_a) * (RSH * 2)
                              + (uint32_t)(ks * 16 + col_a) * 2);
#pragma unroll
            for (int nfp = 0; nfp < 2; nfp++)
                ldmx4(bf[nfp], sB + (uint32_t)(wn * 32 + nfp * 16 + row_b) * (RSH * 2)
                               + (uint32_t)(ks * 16 + col_b) * 2);
#pragma unroll
            for (int mf = 0; mf < 4; mf++)
#pragma unroll
                for (int nfp = 0; nfp < 2; nfp++) {
                    mma16(acc[mf][2 * nfp], af[mf], bf[nfp]);
                    mma16(acc[mf][2 * nfp + 1], af[mf], bf[nfp] + 2);
                }
        }
    }

    // ---- epilogue ----
#pragma unroll
    for (int mf = 0; mf < 4; mf++) {
#pragma unroll
        for (int nf = 0; nf < 4; nf++) {
            const int row = bm * 128 + wm * 64 + mf * 16 + g;
            const int col = bn * 128 + wn * 32 + nf * 8 + 2 * t;
#pragma unroll
            for (int half = 0; half < 2; half++) {
                const int rr = row + half * 8;
                float2 val = make_float2(acc[mf][nf][half * 2], acc[mf][nf][half * 2 + 1]);
                if (mymode == 0) {
                    *(float2*)((float*)Csel + (size_t)rr * N + col) = val;
                } else {
                    const int b = rr >> 11, s = rr & (SS - 1);
                    const int h = col >> 7, hd = col & 127;
                    const size_t idx = ((size_t)(b * HN + h) * SS + s) * HD + hd;
                    if (mymode == 1) *(float2*)((float*)Csel + idx) = val;
                    else ((uint32_t*)Csel)[idx >> 1] = pack_h2(val);
                }
            }
        }
    }
}

// =====================================================================
// Fused RMSNorm + RoPE (+ q scaling): fp32 in (g_q/g_k), PACKED FP16 out
// (g_qh/g_kh). Lane l owns column pairs (2l, 2l+1) and (64+2l, 64+2l+1).
// =====================================================================
__global__ __launch_bounds__(256) void rmsrope(
    const float* __restrict__ cosb, const float* __restrict__ sinb,
    const float* __restrict__ qw, const float* __restrict__ kw) {
    const int wid = threadIdx.x >> 5, lane = threadIdx.x & 31;
    const int row = blockIdx.x * 8 + wid;
    constexpr int QROWS = BB * HH * SS;

    const float* src;
    uint32_t* dst;
    const float* w;
    float extra;
    int s;
    if (row < QROWS) {
        src = g_q + (size_t)row * HD;
        dst = (uint32_t*)g_qh + (size_t)row * (HD / 2);
        w = qw; extra = SCALING; s = row & (SS - 1);
    } else {
        const int r = row - QROWS;
        src = g_k + (size_t)r * HD;
        dst = (uint32_t*)g_kh + (size_t)r * (HD / 2);
        w = kw; extra = 1.0f; s = r & (SS - 1);
    }

    const int c0 = 2 * lane, c1 = 64 + 2 * lane;
    float2 a = *(const float2*)&src[c0];
    float2 bq = *(const float2*)&src[c1];
    float ssq = a.x * a.x + a.y * a.y + bq.x * bq.x + bq.y * bq.y;
#pragma unroll
    for (int o = 16; o; o >>= 1) ssq += __shfl_xor_sync(0xffffffffu, ssq, o);
    const float inv = rsqrtf(ssq * (1.0f / HD) + EPS);

    float2 na = make_float2(a.x * inv * w[c0], a.y * inv * w[c0 + 1]);
    float2 nb = make_float2(bq.x * inv * w[c1], bq.y * inv * w[c1 + 1]);

    const float* cs = cosb + (size_t)s * HD;
    const float* sn = sinb + (size_t)s * HD;
    float2 cA = *(const float2*)&cs[c0], cB = *(const float2*)&cs[c1];
    float2 sA = *(const float2*)&sn[c0], sB = *(const float2*)&sn[c1];

    float2 oa = make_float2((na.x * cA.x - nb.x * sA.x) * extra,
                            (na.y * cA.y - nb.y * sA.y) * extra);
    float2 ob = make_float2((nb.x * cB.x + na.x * sB.x) * extra,
                            (nb.y * cB.y + na.y * sB.y) * extra);

    dst[lane] = pack_h2(oa);
    dst[32 + lane] = pack_h2(ob);
}

// =====================================================================
// Flash attention (causal), fp16 end-to-end: Q/K/V loaded fp16 from gmem
// via cp.async (K/V double-buffered), fp16 smem + ldmatrix, fp16 mma.
// Hot-loop structure = proven R14; loader = proven R9 ring, now zero-cvt.
// =====================================================================
__global__ __launch_bounds__(256, 1) void attn() {
    extern __shared__ uint32_t smw[];
    const int tid = threadIdx.x;
    const int lane = tid & 31, wid = tid >> 5;
    const int g = lane >> 2, t = lane & 3;
    const uint32_t sbase = smem_u32(smw);

    const int row_s = (lane & 7) + 8 * (lane >> 4);
    const int col_s = 8 * ((lane >> 3) & 1);
    const int row_v = (lane & 7) + 8 * ((lane >> 3) & 1);
    const int col_v = 8 * (lane >> 4);

    const int qt = gridDim.x - 1 - blockIdx.x;   // big tiles first
    const int bh = blockIdx.y;
    const int b = bh / HH, h = bh % HH;
    const int kvh = h / (HH / GG);

    const __half* qp = g_qh + ((size_t)(b * HH + h) * SS + qt * 128) * HD;
    const __half* kp = g_kh + ((size_t)(b * GG + kvh) * SS) * HD;
    const __half* vp = g_vh + ((size_t)(b * GG + kvh) * SS) * HD;

    // cp.async K/V tile jt -> stage st. Tile = 64 rows x 256B = 1024 16B-chunks
    // per matrix -> 4 chunks per thread per matrix.
    auto issue_kv = [&](int jt, int st) {
        const uint32_t kb = sbase + (uint32_t)st * KVST_B;
        const uint32_t vb = kb + KT_B;
#pragma unroll
        for (int i = 0; i < 4; i++) {
            const int cc = tid + 256 * i;          // 0..1023
            const int row = cc >> 4, c16 = cc & 15;
            const uint32_t off = (uint32_t)row * (RSW * 4) + c16 * 16;
            cpasync16(kb + off, kp + (size_t)(jt * 64 + row) * HD + c16 * 8);
            cpasync16(vb + off, vp + (size_t)(jt * 64 + row) * HD + c16 * 8);
        }
    };

    issue_kv(0, 0);
    asm volatile("cp.async.commit_group;" ::: "memory");

    // ---- stage Q tile (128 rows x 256B) into the stage-1 region ----
    uint32_t* Qsw = smw + KVST_B / 4;
    {
#pragma unroll
        for (int i = 0; i < 8; i++) {
            const int cc = tid + 256 * i;          // 0..2047
            const int row = cc >> 4, c16 = cc & 15;
            *(uint4*)&Qsw[row * RSW + c16 * 4] =
                *(const uint4*)(qp + (size_t)row * HD + c16 * 8);
        }
    }
    __syncthreads();

    uint32_t qf[8][4];
    {
        const int r = wid * 16;
#pragma unroll
        for (int ks = 0; ks < 8; ks++) {
            const int cw = ks * 8 + t;
            qf[ks][0] = Qsw[(r + g) * RSW + cw];
            qf[ks][1] = Qsw[(r + g + 8) * RSW + cw];
            qf[ks][2] = Qsw[(r + g) * RSW + cw + 4];
            qf[ks][3] = Qsw[(r + g + 8) * RSW + cw + 4];
        }
    }
    __syncthreads();   // stage-1 region now free for K/V tile 1

    float o[16][4];
#pragma unroll
    for (int i = 0; i < 16; i++)
#pragma unroll
        for (int j = 0; j < 4; j++) o[i][j] = 0.f;
    float mprev[2] = {-1e30f, -1e30f};
    float lsum[2] = {0.f, 0.f};

    const int jmax = 2 * qt + 1;
    for (int jt = 0; jt <= jmax; jt++) {
        if (jt + 1 <= jmax) issue_kv(jt + 1, (jt + 1) & 1);
        asm volatile("cp.async.commit_group;" ::: "memory");
        asm volatile("cp.async.wait_group 1;" ::: "memory");   // tile jt resident
        __syncthreads();

        const uint32_t sbK = sbase + (uint32_t)(jt & 1) * KVST_B;
        const uint32_t sbV = sbK + KT_B;

        // ---- scores = Q K^T ----
        float sc[8][4];
#pragma unroll
        for (int i = 0; i < 8; i++)
#pragma unroll
            for (int j = 0; j < 4; j++) sc[i][j] = 0.f;

#pragma unroll
        for (int ks = 0; ks < 8; ks++) {
#pragma unroll
            for (int nfp = 0; nfp < 4; nfp++) {
                uint32_t kf[4];
                const uint32_t addr = sbK +
                    ((uint32_t)(16 * nfp + row_s) * (RSW * 4)) +
                    (uint32_t)(16 * ks + col_s) * 2;
                ldmx4(kf, addr);
                mma16(sc[2 * nfp], qf[ks], kf);
                mma16(sc[2 * nfp + 1], qf[ks], kf + 2);
            }
        }

        // ---- causal mask (diagonal tiles only) ----
        if (jt >= 2 * qt) {
            const int rowg = qt * 128 + wid * 16 + g;
#pragma unroll
            for (int nf = 0; nf < 8; nf++) {
                const int colg = jt * 64 + nf * 8 + 2 * t;
                if (colg > rowg) sc[nf][0] = -1e30f;
                if (colg + 1 > rowg) sc[nf][1] = -1e30f;
                if (colg > rowg + 8) sc[nf][2] = -1e30f;
                if (colg + 1 > rowg + 8) sc[nf][3] = -1e30f;
            }
        }

        // ---- online softmax ----
#pragma unroll
        for (int r = 0; r < 2; r++) {
            float mx = -1e30f;
#pragma unroll
            for (int nf = 0; nf < 8; nf++)
                mx = fmaxf(mx, fmaxf(sc[nf][2 * r], sc[nf][2 * r + 1]));
            mx = fmaxf(mx, __shfl_xor_sync(0xffffffffu, mx, 1));
            mx = fmaxf(mx, __shfl_xor_sync(0xffffffffu, mx, 2));
            const float mnew = fmaxf(mprev[r], mx);
            const float corr = __expf(mprev[r] - mnew);
            float sum = 0.f;
#pragma unroll
            for (int nf = 0; nf < 8; nf++) {
                sc[nf][2 * r] = __expf(sc[nf][2 * r] - mnew);
                sc[nf][2 * r + 1] = __expf(sc[nf][2 * r + 1] - mnew);
                sum += sc[nf][2 * r] + sc[nf][2 * r + 1];
            }
            sum += __shfl_xor_sync(0xffffffffu, sum, 1);
            sum += __shfl_xor_sync(0xffffffffu, sum, 2);
            lsum[r] = lsum[r] * corr + sum;
            mprev[r] = mnew;
#pragma unroll
            for (int nf = 0; nf < 16; nf++) {
                o[nf][2 * r] *= corr;
                o[nf][2 * r + 1] *= corr;
            }
        }

        // ---- O += P V ----
#pragma unroll
        for (int ks = 0; ks < 4; ks++) {
            uint32_t pafr[4];
            pafr[0] = pack_h2(make_float2(sc[2 * ks][0], sc[2 * ks][1]));
            pafr[1] = pack_h2(make_float2(sc[2 * ks][2], sc[2 * ks][3]));
            pafr[2] = pack_h2(make_float2(sc[2 * ks + 1][0], sc[2 * ks + 1][1]));
            pafr[3] = pack_h2(make_float2(sc[2 * ks + 1][2], sc[2 * ks + 1][3]));
#pragma unroll
            for (int nfp = 0; nfp < 8; nfp++) {
                uint32_t vf[4];
                const uint32_t addr = sbV +
                    ((uint32_t)(16 * ks + row_v) * (RSW * 4)) +
                    (uint32_t)(16 * nfp + col_v) * 2;
                ldmx4t(vf, addr);
                mma16(o[2 * nfp], pafr, vf);
                mma16(o[2 * nfp + 1], pafr, vf + 2);
            }
        }
        __syncthreads();   // all warps done with stage jt&1 before next overwrite
    }

    // ---- epilogue: O/l -> ctx (fp16, packed) ----
    uint32_t* ctxw = (uint32_t*)g_ctxh;
    const float inv0 = 1.f / lsum[0];
    const float inv1 = 1.f / lsum[1];
    const int row0 = qt * 128 + wid * 16 + g;
#pragma unroll
    for (int nf = 0; nf < 16; nf++) {
        const int col = nf * 8 + 2 * t;
        ctxw[(((size_t)(b * SS + row0) * (HH * HD)) + h * HD + col) >> 1] =
            pack_h2(make_float2(o[nf][0] * inv0, o[nf][1] * inv0));
        ctxw[(((size_t)(b * SS + row0 + 8) * (HH * HD)) + h * HD + col) >> 1] =
            pack_h2(make_float2(o[nf][2] * inv1, o[nf][3] * inv1));
    }
}

// =====================================================================
// host launcher
// =====================================================================
extern "C" void kernel_launch(void* const* d_in, const int* in_sizes, int n_in,
                              void* d_out, int out_size) {
    (void)in_sizes; (void)n_in; (void)out_size;
    const float* x    = (const float*)d_in[0];
    // d_in[1] = mask (causal triu, known analytically; unused)
    const float* cosb = (const float*)d_in[2];
    const float* sinb = (const float*)d_in[3];
    const float* Wq   = (const float*)d_in[4];
    const float* Wk   = (const float*)d_in[5];
    const float* Wv   = (const float*)d_in[6];
    const float* Wo   = (const float*)d_in[7];
    const float* qw   = (const float*)d_in[8];
    const float* kw   = (const float*)d_in[9];
    float* out = (float*)d_out;

    float *qptr, *kptr;
    __half *xh, *wqh, *wkh, *wvh, *woh, *ctxh, *vh;
    cudaGetSymbolAddress((void**)&qptr, g_q);
    cudaGetSymbolAddress((void**)&kptr, g_k);
    cudaGetSymbolAddress((void**)&vh, g_vh);
    cudaGetSymbolAddress((void**)&xh, g_xh);
    cudaGetSymbolAddress((void**)&wqh, g_wqh);
    cudaGetSymbolAddress((void**)&wkh, g_wkh);
    cudaGetSymbolAddress((void**)&wvh, g_wvh);
    cudaGetSymbolAddress((void**)&woh, g_woh);
    cudaGetSymbolAddress((void**)&ctxh, g_ctxh);

    cudaFuncSetAttribute(gemm_h, cudaFuncAttributeMaxDynamicSharedMemorySize, GEMM_SMEM);
    cudaFuncSetAttribute(attn, cudaFuncAttributeMaxDynamicSharedMemorySize, ATTN_SMEM);

    const int BIG = 1 << 30;
    // 0. fp16 pre-pass (x, Wq, Wk, Wv, Wo)
    tofp16<<<2048, 256>>>((const float4*)x, (const float4*)Wq, (const float4*)Wk,
                          (const float4*)Wv, (const float4*)Wo);
    // 1. Q projection (fp32 head layout; rope input)
    gemm_h<<<dim3(16, 32), 256, GEMM_SMEM>>>(xh, wqh, qptr, wqh, qptr, BIG,
                                             HH * HD, DD, 1, 1, HH);
    // 1b. K (fp32, rope input) + V (fp16 direct) fused
    gemm_h<<<dim3(8, 32), 256, GEMM_SMEM>>>(xh, wkh, kptr, wvh, vh, 4,
                                            GG * HD, DD, 1, 2, GG);
    // 2. RMSNorm + RoPE (+ q scaling): fp32 in -> fp16 out (g_qh, g_kh)
    rmsrope<<<(BB * (HH + GG) * SS) / 8, 256>>>(cosb, sinb, qw, kw);
    // 3. flash attention (fp16 end-to-end, cp.async double-buffered K/V)
    attn<<<dim3(SS / 128, BB * HH), 256, ATTN_SMEM>>>();
    // 4. output projection -> d_out (fp32)
    gemm_h<<<dim3(16, 32), 256, GEMM_SMEM>>>(ctxh, woh, out, woh, out, BIG,
                                             DD, HH * HD, 0, 0, 0);
}